// round 7
// baseline (speedup 1.0000x reference)
#include <cuda_runtime.h>
#include <cuda_bf16.h>

// Problem constants: T=64, B=512, H=512.
#define T_DIM 64
#define B_DIM 512
#define H4    128                     // float4 per row (H=512)
#define STRIDE (B_DIM * H4)           // float4 stride between consecutive t
#define SLOTS 33                      // slot 0 = init row, 1..32 = staged inputs
#define SMEM_BYTES (SLOTS * H4 * 16)  // 33 * 2048 = 67584 B

// One block per batch lane b, 128 threads (thread = one float4 column).
//   src[t] = -1 if P[t]==0 else max{u<=t : P[u-1]==P[t]-1},  P = prefix(ops)
// Distinct source rows are staged in SMEM via cp.async (deep MLP, one
// latency exposure per block), then 64 independent row-stores stream out.
__global__ void __launch_bounds__(128, 3) fused_kernel(
    const float4* __restrict__ inputs,   // (T,B,H) as float4
    const float4* __restrict__ init_h,   // (H,)    as float4
    const int*    __restrict__ ops,      // (T,B)
    float4*       __restrict__ out)      // (T,B,H) as float4
{
    extern __shared__ float4 stage[];        // [SLOTS][H4]
    __shared__ int s_P[T_DIM + 1];           // s_P[u] = P[u-1], s_P[0] = 0
    __shared__ int s_src[T_DIM];
    __shared__ int s_pres[T_DIM];            // presence of source value s
    __shared__ int s_rank[T_DIM];            // inclusive rank among present
    __shared__ int s_slotsrc[SLOTS];         // slot -> source time
    __shared__ int s_slot[T_DIM];            // t -> slot (-1 = direct gmem)
    __shared__ int s_w0, s_w0b, s_n;

    const int b   = blockIdx.x;
    const int tid = threadIdx.x;
    const unsigned mask = 0xFFFFFFFFu;

    // ---- Phase 1a: two-warp inclusive scan of ops column b ----
    int p = 0;
    if (tid < T_DIM) {
        s_pres[tid] = 0;
        p = ops[tid * B_DIM + b];
        #pragma unroll
        for (int d = 1; d < 32; d <<= 1) {
            int n = __shfl_up_sync(mask, p, d);
            if ((tid & 31) >= d) p += n;
        }
        if (tid == 31) s_w0 = p;
        if (tid == 0)  s_P[0] = 0;
    }
    __syncthreads();
    if (tid >= 32 && tid < T_DIM) p += s_w0;
    if (tid < T_DIM) s_P[tid + 1] = p;
    __syncthreads();

    // ---- Phase 1b: per-t backward search for the matching writer ----
    if (tid < T_DIM) {
        int Pt  = s_P[tid + 1];
        int src = -1;
        if (Pt > 0) {
            int target = Pt - 1;
            #pragma unroll 1
            for (int u = tid; u >= 0; --u) {
                if (s_P[u] == target) { src = u; break; }
            }
        }
        s_src[tid] = src;
        if (src >= 0) s_pres[src] = 1;       // benign write races
    }
    __syncthreads();

    // ---- Phase 1c: rank distinct sources (second 2-warp scan) ----
    int r = 0;
    if (tid < T_DIM) {
        r = s_pres[tid];
        #pragma unroll
        for (int d = 1; d < 32; d <<= 1) {
            int n = __shfl_up_sync(mask, r, d);
            if ((tid & 31) >= d) r += n;
        }
        if (tid == 31) s_w0b = r;
    }
    __syncthreads();
    if (tid >= 32 && tid < T_DIM) r += s_w0b;
    if (tid < T_DIM) {
        s_rank[tid] = r;                     // inclusive: present source -> slot r
        if (s_pres[tid] && r <= SLOTS - 1) s_slotsrc[r] = tid;
        if (tid == T_DIM - 1) s_n = r;       // number of distinct sources
    }
    __syncthreads();
    if (tid < T_DIM) {
        int s = s_src[tid];
        int sl;
        if (s < 0) sl = 0;
        else {
            int k = s_rank[s];
            sl = (k <= SLOTS - 1) ? k : -1;  // overflow -> direct gmem
        }
        s_slot[tid] = sl;
    }

    // ---- Phase A: stage init row + distinct source rows via cp.async ----
    {
        unsigned sa0 = (unsigned)__cvta_generic_to_shared(&stage[tid]);
        asm volatile("cp.async.cg.shared.global [%0], [%1], 16;\n"
                     :: "r"(sa0), "l"(init_h + tid));
    }
    __syncthreads();                          // s_slotsrc/s_n visible
    int nstage = min(s_n, SLOTS - 1);
    #pragma unroll 1
    for (int k = 1; k <= nstage; ++k) {
        const float4* g = inputs + ((unsigned)(s_slotsrc[k] * B_DIM + b)) * H4 + tid;
        unsigned sa = (unsigned)__cvta_generic_to_shared(&stage[k * H4 + tid]);
        asm volatile("cp.async.cg.shared.global [%0], [%1], 16;\n"
                     :: "r"(sa), "l"(g));
    }
    asm volatile("cp.async.commit_group;\n" ::: "memory");
    asm volatile("cp.async.wait_group 0;\n" ::: "memory");
    __syncthreads();

    // ---- Phase B: 64 independent row-stores from SMEM ----
    const float4* __restrict__ in_base  = inputs + (unsigned)b * H4 + tid;
    float4*       __restrict__ out_base = out    + (unsigned)b * H4 + tid;

    #pragma unroll 4
    for (int t = 0; t < T_DIM; ++t) {
        int sl = s_slot[t];
        float4 v;
        if (sl >= 0) v = stage[sl * H4 + tid];                       // LDS
        else         v = __ldg(in_base + (unsigned)s_src[t] * STRIDE); // rare
        out_base[(unsigned)t * STRIDE] = v;
    }
}

extern "C" void kernel_launch(void* const* d_in, const int* in_sizes, int n_in,
                              void* d_out, int out_size) {
    const float* inputs = (const float*)d_in[0];   // (T,B,H) f32
    const float* init_h = (const float*)d_in[1];   // (H,)    f32
    const int*   ops    = (const int*)d_in[2];     // (T,B)   i32
    float* out = (float*)d_out;                    // (T,B,H) f32

    cudaFuncSetAttribute(fused_kernel,
                         cudaFuncAttributeMaxDynamicSharedMemorySize, SMEM_BYTES);

    fused_kernel<<<B_DIM, 128, SMEM_BYTES>>>(
        (const float4*)inputs, (const float4*)init_h, ops, (float4*)out);
}

// round 10
// speedup vs baseline: 1.6639x; 1.6639x over previous
#include <cuda_runtime.h>
#include <cuda_bf16.h>

// Problem constants: T=64, B=512, H=512.
#define T_DIM 64
#define B_DIM 512
#define H4    128                    // float4 per row (H=512)
#define STRIDE (B_DIM * H4)          // float4 stride between consecutive t

// Grid: 1024 blocks x 256 threads (R5 champion shape). Block (b, half).
// Phase 1 (parallel):
//   P[t] = prefix_sum(ops)[t]  (P[-1] = 0)
//   src[t] = -1 if P[t]==0 else max{ u<=t : P[u-1]==P[t]-1 }
// Phase 2: gather-copy with 8-deep load batching (MLP=8 per thread).
__global__ void __launch_bounds__(256, 4) fused_kernel(
    const float4* __restrict__ inputs,   // (T,B,H) as float4
    const float4* __restrict__ init_h,   // (H,)    as float4
    const int*    __restrict__ ops,      // (T,B)
    float4*       __restrict__ out)      // (T,B,H) as float4
{
    __shared__ int s_P[T_DIM + 1];       // s_P[u] = P[u-1], s_P[0] = 0
    __shared__ int s_src[T_DIM];
    __shared__ int s_w0;

    const int bid  = blockIdx.x;
    const int b    = bid >> 1;
    const int half = bid & 1;
    const int tid  = threadIdx.x;

    // ---- Phase 1a: two-warp inclusive scan of ops column b ----
    int p = 0;
    if (tid < T_DIM) {
        p = ops[tid * B_DIM + b];
        #pragma unroll
        for (int d = 1; d < 32; d <<= 1) {
            int n = __shfl_up_sync(0xFFFFFFFFu, p, d);
            if ((tid & 31) >= d) p += n;
        }
        if (tid == 31) s_w0 = p;
        if (tid == 0)  s_P[0] = 0;
    }
    __syncthreads();
    if (tid >= 32 && tid < T_DIM) p += s_w0;
    if (tid < T_DIM) s_P[tid + 1] = p;
    __syncthreads();

    // ---- Phase 1b: per-t backward search for the matching writer ----
    if (tid < T_DIM) {
        int Pt  = s_P[tid + 1];
        int src = -1;
        if (Pt > 0) {
            int target = Pt - 1;
            #pragma unroll 1
            for (int u = tid; u >= 0; --u) {
                if (s_P[u] == target) { src = u; break; }
            }
        }
        s_src[tid] = src;
    }
    __syncthreads();

    // ---- Phase 2: gather-copy, two batches of (8 loads -> 8 stores) ----
    const int h4 = (half << 6) + (tid & 63);
    const int t0 = tid >> 6;                       // 0..3; t = t0 + 4*i
    const float4* __restrict__ in_base  = inputs + (unsigned)b * H4 + h4;
    float4*       __restrict__ out_base = out    + (unsigned)b * H4 + h4;
    const float4 vinit = init_h[h4];

    #pragma unroll
    for (int batch = 0; batch < 2; ++batch) {
        int   s[8];
        float4 v[8];
        #pragma unroll
        for (int j = 0; j < 8; ++j)
            s[j] = s_src[t0 + ((batch * 8 + j) << 2)];
        // 8 independent loads issued back-to-back (predicated off for init rows)
        #pragma unroll
        for (int j = 0; j < 8; ++j) {
            v[j] = vinit;
            if (s[j] >= 0)
                v[j] = __ldg(in_base + (unsigned)s[j] * STRIDE);
        }
        #pragma unroll
        for (int j = 0; j < 8; ++j)
            out_base[(unsigned)(t0 + ((batch * 8 + j) << 2)) * STRIDE] = v[j];
    }
}

extern "C" void kernel_launch(void* const* d_in, const int* in_sizes, int n_in,
                              void* d_out, int out_size) {
    const float* inputs = (const float*)d_in[0];   // (T,B,H) f32
    const float* init_h = (const float*)d_in[1];   // (H,)    f32
    const int*   ops    = (const int*)d_in[2];     // (T,B)   i32
    float* out = (float*)d_out;                    // (T,B,H) f32

    fused_kernel<<<2 * B_DIM, 256>>>(
        (const float4*)inputs, (const float4*)init_h, ops, (float4*)out);
}